// round 8
// baseline (speedup 1.0000x reference)
#include <cuda_runtime.h>
#include <cuda_fp16.h>
#include <math.h>

#define NN 80000
#define NE 1280000
#define NG 512
#define FF 64

// ---------------- scratch (device globals, no allocation) ----------------
__device__ __align__(16) float g_hA[NN*FF];
__device__ __align__(16) float g_hB[NN*FF];
__device__ __align__(16) __half g_hA16[NN*FF];
__device__ __align__(16) __half g_hB16[NN*FF];
__device__ __align__(16) float g_x4[NN*4];
__device__ __align__(16) float g_B0[NN*4];
__device__ __align__(16) float g_B1[NN*4];
__device__ __align__(16) float g_pooled[NG*FF];
__device__ int   g_cnt[NN];
__device__ int   g_cursor[NN];
__device__ int   g_off[NN+1];
__device__ int   g_bsum[320];
__device__ int   g_boff[320];
__device__ int   g_esrc[NE];
__device__ float g_eu[NE];

// ---------------- helpers ----------------
__device__ __forceinline__ void red_add_v4(float* p, float4 v) {
    asm volatile("red.global.add.v4.f32 [%0], {%1,%2,%3,%4};"
                 :: "l"(p), "f"(v.x), "f"(v.y), "f"(v.z), "f"(v.w) : "memory");
}
__device__ __forceinline__ float elu1(float v) { return v > 0.0f ? v : expm1f(v); }

// ---------------- CSR build ----------------
__global__ void k_zero() {
    int t = blockIdx.x * blockDim.x + threadIdx.x;
    if (t < NN) { g_cnt[t] = 0; g_cursor[t] = 0; }
    if (t < NG*FF) g_pooled[t] = 0.0f;
}

__global__ void k_hist(const int* __restrict__ dst) {
    int e = blockIdx.x * blockDim.x + threadIdx.x;   // exactly NE threads
    atomicAdd(&g_cnt[dst[e]], 1);
}

__global__ void k_scan1() {
    __shared__ int wsum[8];
    int b = blockIdx.x, tid = threadIdx.x, lane = tid & 31, w = tid >> 5;
    int i = b * 256 + tid;
    int v = (i < NN) ? g_cnt[i] : 0;
    int inc = v;
    #pragma unroll
    for (int o = 1; o < 32; o <<= 1) {
        int nv = __shfl_up_sync(0xffffffffu, inc, o);
        if (lane >= o) inc += nv;
    }
    if (lane == 31) wsum[w] = inc;
    __syncthreads();
    if (w == 0 && lane < 8) {
        int x = wsum[lane];
        int xi = x;
        #pragma unroll
        for (int o = 1; o < 8; o <<= 1) {
            int nv = __shfl_up_sync(0xffu, xi, o, 8);
            if (lane >= o) xi += nv;
        }
        wsum[lane] = xi - x;
        if (lane == 7) g_bsum[b] = xi;
    }
    __syncthreads();
    if (i < NN) g_off[i] = wsum[w] + (inc - v);
}

#define NB_SCAN 313
__global__ void k_scan2() {
    __shared__ int s[512];
    int tid = threadIdx.x;
    int v = (tid < NB_SCAN) ? g_bsum[tid] : 0;
    s[tid] = v;
    __syncthreads();
    for (int o = 1; o < 512; o <<= 1) {
        int t = (tid >= o) ? s[tid - o] : 0;
        __syncthreads();
        s[tid] += t;
        __syncthreads();
    }
    if (tid < NB_SCAN) g_boff[tid] = s[tid] - v;
}

__global__ void k_scan3() {
    int i = blockIdx.x * blockDim.x + threadIdx.x;
    if (i < NN) g_off[i] += g_boff[i >> 8];
    if (i == 0) g_off[NN] = NE;
}

__global__ void k_fill(const int* __restrict__ src, const int* __restrict__ dst,
                       const float* __restrict__ u) {
    int e = blockIdx.x * blockDim.x + threadIdx.x;
    int d = dst[e];
    int pos = g_off[d] + atomicAdd(&g_cursor[d], 1);
    g_esrc[pos] = src[e];
    g_eu[pos]   = u[e];
}

// ---------------- pack x into float4 ----------------
__global__ void k_packx(const float* __restrict__ x) {
    int n = blockIdx.x * blockDim.x + threadIdx.x;
    if (n >= NN) return;
    float4 v; v.x = x[n*3+0]; v.y = x[n*3+1]; v.z = x[n*3+2]; v.w = 0.f;
    ((float4*)g_x4)[n] = v;
}

// ---------------- layer 1: aggregate raw x (3-dim) then transform ----------
__global__ void k_gather3() {
    int n = blockIdx.x * blockDim.x + threadIdx.x;
    if (n >= NN) return;
    int beg = g_off[n], end = g_off[n+1];
    float sa0=0,sa1=0,sa2=0, ta0=0,ta1=0,ta2=0;
    float sb0=0,sb1=0,sb2=0, tb0=0,tb1=0,tb2=0;
    const float4* X4 = (const float4*)g_x4;
    int e = beg;
    for (; e + 1 < end; e += 2) {
        int sA = __ldg(&g_esrc[e]);   float uA = __ldg(&g_eu[e]);
        int sB = __ldg(&g_esrc[e+1]); float uB = __ldg(&g_eu[e+1]);
        float4 xa = __ldg(&X4[sA]);
        float4 xb = __ldg(&X4[sB]);
        sa0 += xa.x; sa1 += xa.y; sa2 += xa.z;
        ta0 += uA*xa.x; ta1 += uA*xa.y; ta2 += uA*xa.z;
        sb0 += xb.x; sb1 += xb.y; sb2 += xb.z;
        tb0 += uB*xb.x; tb1 += uB*xb.y; tb2 += uB*xb.z;
    }
    if (e < end) {
        int sA = __ldg(&g_esrc[e]); float uA = __ldg(&g_eu[e]);
        float4 xa = __ldg(&X4[sA]);
        sa0 += xa.x; sa1 += xa.y; sa2 += xa.z;
        ta0 += uA*xa.x; ta1 += uA*xa.y; ta2 += uA*xa.z;
    }
    float t0 = ta0+tb0, t1 = ta1+tb1, t2 = ta2+tb2;
    g_B0[n*4+0] = (sa0+sb0) - t0; g_B0[n*4+1] = (sa1+sb1) - t1; g_B0[n*4+2] = (sa2+sb2) - t2;
    g_B1[n*4+0] = t0; g_B1[n*4+1] = t1; g_B1[n*4+2] = t2;
}

__global__ void k_layer1(const float* __restrict__ x, const float* __restrict__ W,
                         const float* __restrict__ root, const float* __restrict__ b) {
    int t = blockIdx.x * blockDim.x + threadIdx.x;
    int n = t >> 6, f = t & 63;
    float agg = g_B0[n*4+0]*__ldg(&W[f])      + g_B0[n*4+1]*__ldg(&W[64+f])  + g_B0[n*4+2]*__ldg(&W[128+f])
              + g_B1[n*4+0]*__ldg(&W[192+f])  + g_B1[n*4+1]*__ldg(&W[256+f]) + g_B1[n*4+2]*__ldg(&W[320+f]);
    int dg = g_off[n+1] - g_off[n];
    float inv = 1.0f / (dg < 1 ? 1 : dg);
    float yr = x[n*3+0]*__ldg(&root[f]) + x[n*3+1]*__ldg(&root[64+f]) + x[n*3+2]*__ldg(&root[128+f]);
    float v = elu1(agg*inv + yr + __ldg(&b[f]));
    g_hA[t] = v;
    g_hA16[t] = __float2half_rn(v);
}

// ---------------- fused gather + GEMM layer (layers 2-4) -------------------
__global__ __launch_bounds__(256) void k_glayer(int insel, int outsel,
                                                const float* __restrict__ W,
                                                const float* __restrict__ root,
                                                const float* __restrict__ bias) {
    __shared__ float sF[64 * 192];                  // [node][A0(64)|A1(64)|H(64)]
    const float* hin   = insel  ? g_hB   : g_hA;
    float*       hout  = outsel ? g_hB   : g_hA;
    const __half* h16in  = insel  ? g_hB16 : g_hA16;
    __half*       h16out = outsel ? g_hB16 : g_hA16;
    const int nb = blockIdx.x * 64;
    const int tid = threadIdx.x;
    const int lane = tid & 31;
    const int warp = tid >> 5;
    const int j = lane & 15;
    const int half = lane >> 4;

    float4* sF4 = (float4*)sF;
    const float4* H4 = (const float4*)hin;
    const uint2* H16 = (const uint2*)h16in;         // 16 uint2 per 64-half row

    // stage H rows (fp32, exact) into sF[.][128..191]
    for (int i = tid; i < 64*16; i += 256) {
        int r = i >> 4, jj = i & 15;
        sF4[r*48 + 32 + jj] = H4[(long)(nb + r)*16 + jj];
    }

    // gather from fp16 H: 1 warp per node, 2 edges in flight per half-warp
    for (int q = 0; q < 8; ++q) {
        int n = nb + warp*8 + q;
        int beg = g_off[n], end = g_off[n+1];
        int d = end - beg;
        float inv = 1.0f / (d < 1 ? 1 : d);
        int mid = beg + ((d + 1) >> 1);
        int e0 = half ? mid : beg;
        int e1 = half ? end : mid;
        float4 sa = make_float4(0.f,0.f,0.f,0.f), ta = make_float4(0.f,0.f,0.f,0.f);
        float4 sb = make_float4(0.f,0.f,0.f,0.f), tb = make_float4(0.f,0.f,0.f,0.f);
        int e = e0;
        for (; e + 1 < e1; e += 2) {
            int  iA = __ldg(&g_esrc[e]);
            int  iB = __ldg(&g_esrc[e+1]);
            float uA = __ldg(&g_eu[e]);
            float uB = __ldg(&g_eu[e+1]);
            uint2 vA = __ldg(&H16[(long)iA*16 + j]);
            uint2 vB = __ldg(&H16[(long)iB*16 + j]);
            float2 a01 = __half22float2(*(__half2*)&vA.x);
            float2 a23 = __half22float2(*(__half2*)&vA.y);
            float2 b01 = __half22float2(*(__half2*)&vB.x);
            float2 b23 = __half22float2(*(__half2*)&vB.y);
            sa.x += a01.x; sa.y += a01.y; sa.z += a23.x; sa.w += a23.y;
            ta.x += uA*a01.x; ta.y += uA*a01.y; ta.z += uA*a23.x; ta.w += uA*a23.y;
            sb.x += b01.x; sb.y += b01.y; sb.z += b23.x; sb.w += b23.y;
            tb.x += uB*b01.x; tb.y += uB*b01.y; tb.z += uB*b23.x; tb.w += uB*b23.y;
        }
        if (e < e1) {
            int  iA = __ldg(&g_esrc[e]);
            float uA = __ldg(&g_eu[e]);
            uint2 vA = __ldg(&H16[(long)iA*16 + j]);
            float2 a01 = __half22float2(*(__half2*)&vA.x);
            float2 a23 = __half22float2(*(__half2*)&vA.y);
            sa.x += a01.x; sa.y += a01.y; sa.z += a23.x; sa.w += a23.y;
            ta.x += uA*a01.x; ta.y += uA*a01.y; ta.z += uA*a23.x; ta.w += uA*a23.y;
        }
        float4 sum, t;
        sum.x = sa.x + sb.x; sum.y = sa.y + sb.y; sum.z = sa.z + sb.z; sum.w = sa.w + sb.w;
        t.x = ta.x + tb.x; t.y = ta.y + tb.y; t.z = ta.z + tb.z; t.w = ta.w + tb.w;
        sum.x += __shfl_xor_sync(0xffffffffu, sum.x, 16);
        sum.y += __shfl_xor_sync(0xffffffffu, sum.y, 16);
        sum.z += __shfl_xor_sync(0xffffffffu, sum.z, 16);
        sum.w += __shfl_xor_sync(0xffffffffu, sum.w, 16);
        t.x += __shfl_xor_sync(0xffffffffu, t.x, 16);
        t.y += __shfl_xor_sync(0xffffffffu, t.y, 16);
        t.z += __shfl_xor_sync(0xffffffffu, t.z, 16);
        t.w += __shfl_xor_sync(0xffffffffu, t.w, 16);
        int r = warp*8 + q;
        if (half == 0) {   // A0 = (sum - t) * inv
            float4 o;
            o.x = (sum.x - t.x) * inv; o.y = (sum.y - t.y) * inv;
            o.z = (sum.z - t.z) * inv; o.w = (sum.w - t.w) * inv;
            sF4[r*48 + j] = o;
        } else {           // A1 = t * inv
            float4 o;
            o.x = t.x * inv; o.y = t.y * inv; o.z = t.z * inv; o.w = t.w * inv;
            sF4[r*48 + 16 + j] = o;
        }
    }
    __syncthreads();

    // GEMM (fp32): thread tile = 4 nodes x 4 cols
    const int f4 = tid & 15;
    const int mg = tid >> 4;

    float acc[4][4];
    #pragma unroll
    for (int i = 0; i < 4; ++i)
        #pragma unroll
        for (int c = 0; c < 4; ++c) acc[i][c] = 0.f;

    const float4* W4 = (const float4*)W;
    const float4* R4 = (const float4*)root;

    #pragma unroll 4
    for (int kc = 0; kc < 32; ++kc) {
        float4 w0 = __ldg(&W4[(4*kc+0)*16 + f4]);
        float4 w1 = __ldg(&W4[(4*kc+1)*16 + f4]);
        float4 w2 = __ldg(&W4[(4*kc+2)*16 + f4]);
        float4 w3 = __ldg(&W4[(4*kc+3)*16 + f4]);
        #pragma unroll
        for (int i = 0; i < 4; ++i) {
            int r = mg*4 + i;
            float4 xv = sF4[r*48 + kc];
            acc[i][0] += xv.x*w0.x + xv.y*w1.x + xv.z*w2.x + xv.w*w3.x;
            acc[i][1] += xv.x*w0.y + xv.y*w1.y + xv.z*w2.y + xv.w*w3.y;
            acc[i][2] += xv.x*w0.z + xv.y*w1.z + xv.z*w2.z + xv.w*w3.z;
            acc[i][3] += xv.x*w0.w + xv.y*w1.w + xv.z*w2.w + xv.w*w3.w;
        }
    }
    #pragma unroll 4
    for (int kc = 0; kc < 16; ++kc) {
        float4 w0 = __ldg(&R4[(4*kc+0)*16 + f4]);
        float4 w1 = __ldg(&R4[(4*kc+1)*16 + f4]);
        float4 w2 = __ldg(&R4[(4*kc+2)*16 + f4]);
        float4 w3 = __ldg(&R4[(4*kc+3)*16 + f4]);
        #pragma unroll
        for (int i = 0; i < 4; ++i) {
            int r = mg*4 + i;
            float4 xv = sF4[r*48 + 32 + kc];
            acc[i][0] += xv.x*w0.x + xv.y*w1.x + xv.z*w2.x + xv.w*w3.x;
            acc[i][1] += xv.x*w0.y + xv.y*w1.y + xv.z*w2.y + xv.w*w3.y;
            acc[i][2] += xv.x*w0.z + xv.y*w1.z + xv.z*w2.z + xv.w*w3.z;
            acc[i][3] += xv.x*w0.w + xv.y*w1.w + xv.z*w2.w + xv.w*w3.w;
        }
    }

    float4 bv = __ldg(&((const float4*)bias)[f4]);
    #pragma unroll
    for (int i = 0; i < 4; ++i) {
        int n = nb + mg*4 + i;
        float4 o;
        o.x = elu1(acc[i][0] + bv.x);
        o.y = elu1(acc[i][1] + bv.y);
        o.z = elu1(acc[i][2] + bv.z);
        o.w = elu1(acc[i][3] + bv.w);
        ((float4*)(hout + (long)n*64))[f4] = o;
        __half2 p0 = __floats2half2_rn(o.x, o.y);
        __half2 p1 = __floats2half2_rn(o.z, o.w);
        uint2 pk; pk.x = *(unsigned*)&p0; pk.y = *(unsigned*)&p1;
        ((uint2*)(h16out + (long)n*64))[f4] = pk;
    }
}

// ---------------- pooling ----------------
#define POOL_CHUNK 64
#define POOL_NCHUNK ((NN + POOL_CHUNK - 1) / POOL_CHUNK)   // 1250
__global__ void k_pool(const int* __restrict__ batch) {
    int t = blockIdx.x * blockDim.x + threadIdx.x;
    int j = t & 15;
    int c = t >> 4;
    if (c >= POOL_NCHUNK) return;
    int n0 = c * POOL_CHUNK;
    int n1 = n0 + POOL_CHUNK; if (n1 > NN) n1 = NN;
    const float4* h4 = (const float4*)g_hB;
    float4 acc = make_float4(0.f,0.f,0.f,0.f);
    int g = batch[n0];
    for (int n = n0; n < n1; ++n) {
        int gg = batch[n];
        if (gg != g) {
            red_add_v4(&g_pooled[g*64 + j*4], acc);
            acc = make_float4(0.f,0.f,0.f,0.f);
            g = gg;
        }
        float4 v = h4[(long)n*16 + j];
        acc.x += v.x; acc.y += v.y; acc.z += v.z; acc.w += v.w;
    }
    red_add_v4(&g_pooled[g*64 + j*4], acc);
}

// ---------------- head ----------------
__global__ void k_head(const int* __restrict__ batch, const float* __restrict__ fcw,
                       const float* __restrict__ fcb, float* __restrict__ out) {
    int g = blockIdx.x * blockDim.x + threadIdx.x;
    if (g >= NG) return;
    int lo, hi, c0, c1;
    lo = 0; hi = NN;
    while (lo < hi) { int mid = (lo + hi) >> 1; if (batch[mid] < g) lo = mid + 1; else hi = mid; }
    c0 = lo;
    lo = 0; hi = NN;
    while (lo < hi) { int mid = (lo + hi) >> 1; if (batch[mid] < g + 1) lo = mid + 1; else hi = mid; }
    c1 = lo;
    float cnt = (float)(c1 - c0);
    float inv = 1.0f / (cnt < 1.0f ? 1.0f : cnt);

    float logit[6];
    #pragma unroll
    for (int cc = 0; cc < 6; ++cc) logit[cc] = fcb[cc];
    for (int k = 0; k < 64; ++k) {
        float p = g_pooled[g*64 + k] * inv;
        #pragma unroll
        for (int cc = 0; cc < 6; ++cc) logit[cc] += p * fcw[k*6 + cc];
    }
    float m = logit[0];
    #pragma unroll
    for (int cc = 1; cc < 6; ++cc) m = fmaxf(m, logit[cc]);
    float s = 0.f;
    #pragma unroll
    for (int cc = 0; cc < 6; ++cc) s += expf(logit[cc] - m);
    float l = logf(s);
    #pragma unroll
    for (int cc = 0; cc < 6; ++cc) out[g*6 + cc] = logit[cc] - m - l;
}

// ---------------- launch ----------------
extern "C" void kernel_launch(void* const* d_in, const int* in_sizes, int n_in,
                              void* d_out, int out_size) {
    const float* x      = (const float*)d_in[0];
    const float* pseudo = (const float*)d_in[1];
    const int*   ei     = (const int*)d_in[2];
    const int*   batch  = (const int*)d_in[3];
    const float* W1 = (const float*)d_in[4];
    const float* r1 = (const float*)d_in[5];
    const float* b1 = (const float*)d_in[6];
    const float* W2 = (const float*)d_in[7];
    const float* r2 = (const float*)d_in[8];
    const float* b2 = (const float*)d_in[9];
    const float* W3 = (const float*)d_in[10];
    const float* r3 = (const float*)d_in[11];
    const float* b3 = (const float*)d_in[12];
    const float* W4 = (const float*)d_in[13];
    const float* r4 = (const float*)d_in[14];
    const float* b4 = (const float*)d_in[15];
    const float* fcw = (const float*)d_in[16];
    const float* fcb = (const float*)d_in[17];
    float* out = (float*)d_out;

    const int* src = ei;
    const int* dst = ei + NE;

    // CSR build
    k_zero<<<(NN + 255)/256, 256>>>();
    k_hist<<<NE/256, 256>>>(dst);
    k_scan1<<<NB_SCAN, 256>>>();
    k_scan2<<<1, 512>>>();
    k_scan3<<<NB_SCAN, 256>>>();
    k_fill<<<NE/256, 256>>>(src, dst, pseudo);
    k_packx<<<(NN + 255)/256, 256>>>(x);

    // layer 1 (Fin=3)
    k_gather3<<<(NN + 255)/256, 256>>>();
    k_layer1<<<(NN*FF)/256, 256>>>(x, W1, r1, b1);           // -> hA (+fp16)

    // layers 2-4: fused gather+GEMM
    k_glayer<<<NN/64, 256>>>(0, 1, W2, r2, b2);              // hA -> hB
    k_glayer<<<NN/64, 256>>>(1, 0, W3, r3, b3);              // hB -> hA
    k_glayer<<<NN/64, 256>>>(0, 1, W4, r4, b4);              // hA -> hB

    // pooling + head
    k_pool<<<(POOL_NCHUNK*16 + 255)/256, 256>>>(batch);
    k_head<<<(NG + 255)/256, 256>>>(batch, fcw, fcb, out);
}

// round 9
// speedup vs baseline: 1.0507x; 1.0507x over previous
#include <cuda_runtime.h>
#include <math.h>

#define NN 80000
#define NE 1280000
#define NG 512
#define FF 64

// ---------------- scratch (device globals, no allocation) ----------------
__device__ __align__(16) float g_hA[NN*FF];
__device__ __align__(16) float g_hB[NN*FF];
__device__ __align__(16) float g_x4[NN*4];
__device__ __align__(16) float g_B0[NN*4];
__device__ __align__(16) float g_B1[NN*4];
__device__ __align__(16) float g_pooled[NG*FF];
__device__ int   g_cnt[NN];
__device__ int   g_cursor[NN];
__device__ int   g_off[NN+1];
__device__ int   g_bsum[320];
__device__ int   g_boff[320];
__device__ int   g_esrc[NE];
__device__ float g_eu[NE];

// ---------------- helpers ----------------
__device__ __forceinline__ void red_add_v4(float* p, float4 v) {
    asm volatile("red.global.add.v4.f32 [%0], {%1,%2,%3,%4};"
                 :: "l"(p), "f"(v.x), "f"(v.y), "f"(v.z), "f"(v.w) : "memory");
}
__device__ __forceinline__ float elu1(float v) { return v > 0.0f ? v : expm1f(v); }

// ---------------- CSR build ----------------
__global__ void k_zero() {
    int t = blockIdx.x * blockDim.x + threadIdx.x;
    if (t < NN) { g_cnt[t] = 0; g_cursor[t] = 0; }
    if (t < NG*FF) g_pooled[t] = 0.0f;
}

__global__ void k_hist(const int* __restrict__ dst) {
    int e = blockIdx.x * blockDim.x + threadIdx.x;   // exactly NE threads
    atomicAdd(&g_cnt[dst[e]], 1);
}

__global__ void k_scan1() {
    __shared__ int wsum[8];
    int b = blockIdx.x, tid = threadIdx.x, lane = tid & 31, w = tid >> 5;
    int i = b * 256 + tid;
    int v = (i < NN) ? g_cnt[i] : 0;
    int inc = v;
    #pragma unroll
    for (int o = 1; o < 32; o <<= 1) {
        int nv = __shfl_up_sync(0xffffffffu, inc, o);
        if (lane >= o) inc += nv;
    }
    if (lane == 31) wsum[w] = inc;
    __syncthreads();
    if (w == 0 && lane < 8) {
        int x = wsum[lane];
        int xi = x;
        #pragma unroll
        for (int o = 1; o < 8; o <<= 1) {
            int nv = __shfl_up_sync(0xffu, xi, o, 8);
            if (lane >= o) xi += nv;
        }
        wsum[lane] = xi - x;
        if (lane == 7) g_bsum[b] = xi;
    }
    __syncthreads();
    if (i < NN) g_off[i] = wsum[w] + (inc - v);
}

#define NB_SCAN 313
__global__ void k_scan2() {
    __shared__ int s[512];
    int tid = threadIdx.x;
    int v = (tid < NB_SCAN) ? g_bsum[tid] : 0;
    s[tid] = v;
    __syncthreads();
    for (int o = 1; o < 512; o <<= 1) {
        int t = (tid >= o) ? s[tid - o] : 0;
        __syncthreads();
        s[tid] += t;
        __syncthreads();
    }
    if (tid < NB_SCAN) g_boff[tid] = s[tid] - v;
}

__global__ void k_scan3() {
    int i = blockIdx.x * blockDim.x + threadIdx.x;
    if (i < NN) g_off[i] += g_boff[i >> 8];
    if (i == 0) g_off[NN] = NE;
}

__global__ void k_fill(const int* __restrict__ src, const int* __restrict__ dst,
                       const float* __restrict__ u) {
    int e = blockIdx.x * blockDim.x + threadIdx.x;
    int d = dst[e];
    int pos = g_off[d] + atomicAdd(&g_cursor[d], 1);
    g_esrc[pos] = src[e];
    g_eu[pos]   = u[e];
}

// ---------------- pack x into float4 ----------------
__global__ void k_packx(const float* __restrict__ x) {
    int n = blockIdx.x * blockDim.x + threadIdx.x;
    if (n >= NN) return;
    float4 v; v.x = x[n*3+0]; v.y = x[n*3+1]; v.z = x[n*3+2]; v.w = 0.f;
    ((float4*)g_x4)[n] = v;
}

// ---------------- layer 1: aggregate raw x (3-dim) then transform ----------
__global__ void k_gather3() {
    int n = blockIdx.x * blockDim.x + threadIdx.x;
    if (n >= NN) return;
    int beg = g_off[n], end = g_off[n+1];
    float sa0=0,sa1=0,sa2=0, ta0=0,ta1=0,ta2=0;
    float sb0=0,sb1=0,sb2=0, tb0=0,tb1=0,tb2=0;
    const float4* X4 = (const float4*)g_x4;
    int e = beg;
    for (; e + 1 < end; e += 2) {
        int sA = __ldg(&g_esrc[e]);   float uA = __ldg(&g_eu[e]);
        int sB = __ldg(&g_esrc[e+1]); float uB = __ldg(&g_eu[e+1]);
        float4 xa = __ldg(&X4[sA]);
        float4 xb = __ldg(&X4[sB]);
        sa0 += xa.x; sa1 += xa.y; sa2 += xa.z;
        ta0 += uA*xa.x; ta1 += uA*xa.y; ta2 += uA*xa.z;
        sb0 += xb.x; sb1 += xb.y; sb2 += xb.z;
        tb0 += uB*xb.x; tb1 += uB*xb.y; tb2 += uB*xb.z;
    }
    if (e < end) {
        int sA = __ldg(&g_esrc[e]); float uA = __ldg(&g_eu[e]);
        float4 xa = __ldg(&X4[sA]);
        sa0 += xa.x; sa1 += xa.y; sa2 += xa.z;
        ta0 += uA*xa.x; ta1 += uA*xa.y; ta2 += uA*xa.z;
    }
    float t0 = ta0+tb0, t1 = ta1+tb1, t2 = ta2+tb2;
    g_B0[n*4+0] = (sa0+sb0) - t0; g_B0[n*4+1] = (sa1+sb1) - t1; g_B0[n*4+2] = (sa2+sb2) - t2;
    g_B1[n*4+0] = t0; g_B1[n*4+1] = t1; g_B1[n*4+2] = t2;
}

__global__ void k_layer1(const float* __restrict__ x, const float* __restrict__ W,
                         const float* __restrict__ root, const float* __restrict__ b) {
    int t = blockIdx.x * blockDim.x + threadIdx.x;
    int n = t >> 6, f = t & 63;
    float agg = g_B0[n*4+0]*__ldg(&W[f])      + g_B0[n*4+1]*__ldg(&W[64+f])  + g_B0[n*4+2]*__ldg(&W[128+f])
              + g_B1[n*4+0]*__ldg(&W[192+f])  + g_B1[n*4+1]*__ldg(&W[256+f]) + g_B1[n*4+2]*__ldg(&W[320+f]);
    int dg = g_off[n+1] - g_off[n];
    float inv = 1.0f / (dg < 1 ? 1 : dg);
    float yr = x[n*3+0]*__ldg(&root[f]) + x[n*3+1]*__ldg(&root[64+f]) + x[n*3+2]*__ldg(&root[128+f]);
    g_hA[t] = elu1(agg*inv + yr + __ldg(&b[f]));
}

// ---------------- fused gather + GEMM layer (layers 2-4) -------------------
// h_out = elu( [A0*inv | A1*inv | H] @ [W0; W1; root] + b )
// Gather phase: 1 warp per node, 16 lanes cover the 64-float row (float4/lane),
// 4 independent edges in flight per half-warp (MLP=8/warp).
__global__ __launch_bounds__(256) void k_glayer(int insel, int outsel,
                                                const float* __restrict__ W,
                                                const float* __restrict__ root,
                                                const float* __restrict__ bias) {
    __shared__ float sF[64 * 192];                  // [node][A0(64)|A1(64)|H(64)]
    const float* hin  = insel  ? g_hB : g_hA;
    float*       hout = outsel ? g_hB : g_hA;
    const int nb = blockIdx.x * 64;
    const int tid = threadIdx.x;
    const int lane = tid & 31;
    const int warp = tid >> 5;
    const int j = lane & 15;
    const int half = lane >> 4;

    float4* sF4 = (float4*)sF;
    const float4* H4 = (const float4*)hin;

    // stage H rows into sF[.][128..191]
    for (int i = tid; i < 64*16; i += 256) {
        int r = i >> 4, jj = i & 15;
        sF4[r*48 + 32 + jj] = H4[(long)(nb + r)*16 + jj];
    }

    // gather
    for (int q = 0; q < 8; ++q) {
        int n = nb + warp*8 + q;
        int beg = g_off[n], end = g_off[n+1];
        int d = end - beg;
        float inv = 1.0f / (d < 1 ? 1 : d);
        int mid = beg + ((d + 1) >> 1);
        int e0 = half ? mid : beg;
        int e1 = half ? end : mid;

        float4 s0 = make_float4(0.f,0.f,0.f,0.f), t0 = make_float4(0.f,0.f,0.f,0.f);
        float4 s1 = make_float4(0.f,0.f,0.f,0.f), t1 = make_float4(0.f,0.f,0.f,0.f);
        float4 s2 = make_float4(0.f,0.f,0.f,0.f), t2 = make_float4(0.f,0.f,0.f,0.f);
        float4 s3 = make_float4(0.f,0.f,0.f,0.f), t3 = make_float4(0.f,0.f,0.f,0.f);

        int e = e0;
        for (; e + 3 < e1; e += 4) {
            // issue all index/u loads first, then all row loads (4-deep MLP)
            int  iA = __ldg(&g_esrc[e+0]);
            int  iB = __ldg(&g_esrc[e+1]);
            int  iC = __ldg(&g_esrc[e+2]);
            int  iD = __ldg(&g_esrc[e+3]);
            float uA = __ldg(&g_eu[e+0]);
            float uB = __ldg(&g_eu[e+1]);
            float uC = __ldg(&g_eu[e+2]);
            float uD = __ldg(&g_eu[e+3]);
            float4 vA = H4[(long)iA*16 + j];
            float4 vB = H4[(long)iB*16 + j];
            float4 vC = H4[(long)iC*16 + j];
            float4 vD = H4[(long)iD*16 + j];
            s0.x += vA.x; s0.y += vA.y; s0.z += vA.z; s0.w += vA.w;
            t0.x += uA*vA.x; t0.y += uA*vA.y; t0.z += uA*vA.z; t0.w += uA*vA.w;
            s1.x += vB.x; s1.y += vB.y; s1.z += vB.z; s1.w += vB.w;
            t1.x += uB*vB.x; t1.y += uB*vB.y; t1.z += uB*vB.z; t1.w += uB*vB.w;
            s2.x += vC.x; s2.y += vC.y; s2.z += vC.z; s2.w += vC.w;
            t2.x += uC*vC.x; t2.y += uC*vC.y; t2.z += uC*vC.z; t2.w += uC*vC.w;
            s3.x += vD.x; s3.y += vD.y; s3.z += vD.z; s3.w += vD.w;
            t3.x += uD*vD.x; t3.y += uD*vD.y; t3.z += uD*vD.z; t3.w += uD*vD.w;
        }
        for (; e < e1; ++e) {
            int  iA = __ldg(&g_esrc[e]);
            float uA = __ldg(&g_eu[e]);
            float4 vA = H4[(long)iA*16 + j];
            s0.x += vA.x; s0.y += vA.y; s0.z += vA.z; s0.w += vA.w;
            t0.x += uA*vA.x; t0.y += uA*vA.y; t0.z += uA*vA.z; t0.w += uA*vA.w;
        }

        float4 sum, t;
        sum.x = (s0.x+s1.x) + (s2.x+s3.x);
        sum.y = (s0.y+s1.y) + (s2.y+s3.y);
        sum.z = (s0.z+s1.z) + (s2.z+s3.z);
        sum.w = (s0.w+s1.w) + (s2.w+s3.w);
        t.x = (t0.x+t1.x) + (t2.x+t3.x);
        t.y = (t0.y+t1.y) + (t2.y+t3.y);
        t.z = (t0.z+t1.z) + (t2.z+t3.z);
        t.w = (t0.w+t1.w) + (t2.w+t3.w);

        sum.x += __shfl_xor_sync(0xffffffffu, sum.x, 16);
        sum.y += __shfl_xor_sync(0xffffffffu, sum.y, 16);
        sum.z += __shfl_xor_sync(0xffffffffu, sum.z, 16);
        sum.w += __shfl_xor_sync(0xffffffffu, sum.w, 16);
        t.x += __shfl_xor_sync(0xffffffffu, t.x, 16);
        t.y += __shfl_xor_sync(0xffffffffu, t.y, 16);
        t.z += __shfl_xor_sync(0xffffffffu, t.z, 16);
        t.w += __shfl_xor_sync(0xffffffffu, t.w, 16);

        int r = warp*8 + q;
        if (half == 0) {   // A0 = (sum - t) * inv
            float4 o;
            o.x = (sum.x - t.x) * inv; o.y = (sum.y - t.y) * inv;
            o.z = (sum.z - t.z) * inv; o.w = (sum.w - t.w) * inv;
            sF4[r*48 + j] = o;
        } else {           // A1 = t * inv
            float4 o;
            o.x = t.x * inv; o.y = t.y * inv; o.z = t.z * inv; o.w = t.w * inv;
            sF4[r*48 + 16 + j] = o;
        }
    }
    __syncthreads();

    // GEMM (fp32): thread tile = 4 nodes x 4 cols, k-chunks of 4 via float4
    const int f4 = tid & 15;
    const int mg = tid >> 4;

    float acc[4][4];
    #pragma unroll
    for (int i = 0; i < 4; ++i)
        #pragma unroll
        for (int c = 0; c < 4; ++c) acc[i][c] = 0.f;

    const float4* W4 = (const float4*)W;
    const float4* R4 = (const float4*)root;

    #pragma unroll 4
    for (int kc = 0; kc < 32; ++kc) {
        float4 w0 = __ldg(&W4[(4*kc+0)*16 + f4]);
        float4 w1 = __ldg(&W4[(4*kc+1)*16 + f4]);
        float4 w2 = __ldg(&W4[(4*kc+2)*16 + f4]);
        float4 w3 = __ldg(&W4[(4*kc+3)*16 + f4]);
        #pragma unroll
        for (int i = 0; i < 4; ++i) {
            int r = mg*4 + i;
            float4 xv = sF4[r*48 + kc];
            acc[i][0] += xv.x*w0.x + xv.y*w1.x + xv.z*w2.x + xv.w*w3.x;
            acc[i][1] += xv.x*w0.y + xv.y*w1.y + xv.z*w2.y + xv.w*w3.y;
            acc[i][2] += xv.x*w0.z + xv.y*w1.z + xv.z*w2.z + xv.w*w3.z;
            acc[i][3] += xv.x*w0.w + xv.y*w1.w + xv.z*w2.w + xv.w*w3.w;
        }
    }
    #pragma unroll 4
    for (int kc = 0; kc < 16; ++kc) {
        float4 w0 = __ldg(&R4[(4*kc+0)*16 + f4]);
        float4 w1 = __ldg(&R4[(4*kc+1)*16 + f4]);
        float4 w2 = __ldg(&R4[(4*kc+2)*16 + f4]);
        float4 w3 = __ldg(&R4[(4*kc+3)*16 + f4]);
        #pragma unroll
        for (int i = 0; i < 4; ++i) {
            int r = mg*4 + i;
            float4 xv = sF4[r*48 + 32 + kc];
            acc[i][0] += xv.x*w0.x + xv.y*w1.x + xv.z*w2.x + xv.w*w3.x;
            acc[i][1] += xv.x*w0.y + xv.y*w1.y + xv.z*w2.y + xv.w*w3.y;
            acc[i][2] += xv.x*w0.z + xv.y*w1.z + xv.z*w2.z + xv.w*w3.z;
            acc[i][3] += xv.x*w0.w + xv.y*w1.w + xv.z*w2.w + xv.w*w3.w;
        }
    }

    float4 bv = __ldg(&((const float4*)bias)[f4]);
    #pragma unroll
    for (int i = 0; i < 4; ++i) {
        int n = nb + mg*4 + i;
        float4 o;
        o.x = elu1(acc[i][0] + bv.x);
        o.y = elu1(acc[i][1] + bv.y);
        o.z = elu1(acc[i][2] + bv.z);
        o.w = elu1(acc[i][3] + bv.w);
        ((float4*)(hout + (long)n*64))[f4] = o;
    }
}

// ---------------- pooling ----------------
#define POOL_CHUNK 64
#define POOL_NCHUNK ((NN + POOL_CHUNK - 1) / POOL_CHUNK)   // 1250
__global__ void k_pool(const int* __restrict__ batch) {
    int t = blockIdx.x * blockDim.x + threadIdx.x;
    int j = t & 15;
    int c = t >> 4;
    if (c >= POOL_NCHUNK) return;
    int n0 = c * POOL_CHUNK;
    int n1 = n0 + POOL_CHUNK; if (n1 > NN) n1 = NN;
    const float4* h4 = (const float4*)g_hB;
    float4 acc = make_float4(0.f,0.f,0.f,0.f);
    int g = batch[n0];
    for (int n = n0; n < n1; ++n) {
        int gg = batch[n];
        if (gg != g) {
            red_add_v4(&g_pooled[g*64 + j*4], acc);
            acc = make_float4(0.f,0.f,0.f,0.f);
            g = gg;
        }
        float4 v = h4[(long)n*16 + j];
        acc.x += v.x; acc.y += v.y; acc.z += v.z; acc.w += v.w;
    }
    red_add_v4(&g_pooled[g*64 + j*4], acc);
}

// ---------------- head ----------------
__global__ void k_head(const int* __restrict__ batch, const float* __restrict__ fcw,
                       const float* __restrict__ fcb, float* __restrict__ out) {
    int g = blockIdx.x * blockDim.x + threadIdx.x;
    if (g >= NG) return;
    int lo, hi, c0, c1;
    lo = 0; hi = NN;
    while (lo < hi) { int mid = (lo + hi) >> 1; if (batch[mid] < g) lo = mid + 1; else hi = mid; }
    c0 = lo;
    lo = 0; hi = NN;
    while (lo < hi) { int mid = (lo + hi) >> 1; if (batch[mid] < g + 1) lo = mid + 1; else hi = mid; }
    c1 = lo;
    float cnt = (float)(c1 - c0);
    float inv = 1.0f / (cnt < 1.0f ? 1.0f : cnt);

    float logit[6];
    #pragma unroll
    for (int cc = 0; cc < 6; ++cc) logit[cc] = fcb[cc];
    for (int k = 0; k < 64; ++k) {
        float p = g_pooled[g*64 + k] * inv;
        #pragma unroll
        for (int cc = 0; cc < 6; ++cc) logit[cc] += p * fcw[k*6 + cc];
    }
    float m = logit[0];
    #pragma unroll
    for (int cc = 1; cc < 6; ++cc) m = fmaxf(m, logit[cc]);
    float s = 0.f;
    #pragma unroll
    for (int cc = 0; cc < 6; ++cc) s += expf(logit[cc] - m);
    float l = logf(s);
    #pragma unroll
    for (int cc = 0; cc < 6; ++cc) out[g*6 + cc] = logit[cc] - m - l;
}

// ---------------- launch ----------------
extern "C" void kernel_launch(void* const* d_in, const int* in_sizes, int n_in,
                              void* d_out, int out_size) {
    const float* x      = (const float*)d_in[0];
    const float* pseudo = (const float*)d_in[1];
    const int*   ei     = (const int*)d_in[2];
    const int*   batch  = (const int*)d_in[3];
    const float* W1 = (const float*)d_in[4];
    const float* r1 = (const float*)d_in[5];
    const float* b1 = (const float*)d_in[6];
    const float* W2 = (const float*)d_in[7];
    const float* r2 = (const float*)d_in[8];
    const float* b2 = (const float*)d_in[9];
    const float* W3 = (const float*)d_in[10];
    const float* r3 = (const float*)d_in[11];
    const float* b3 = (const float*)d_in[12];
    const float* W4 = (const float*)d_in[13];
    const float* r4 = (const float*)d_in[14];
    const float* b4 = (const float*)d_in[15];
    const float* fcw = (const float*)d_in[16];
    const float* fcb = (const float*)d_in[17];
    float* out = (float*)d_out;

    const int* src = ei;
    const int* dst = ei + NE;

    // CSR build
    k_zero<<<(NN + 255)/256, 256>>>();
    k_hist<<<NE/256, 256>>>(dst);
    k_scan1<<<NB_SCAN, 256>>>();
    k_scan2<<<1, 512>>>();
    k_scan3<<<NB_SCAN, 256>>>();
    k_fill<<<NE/256, 256>>>(src, dst, pseudo);
    k_packx<<<(NN + 255)/256, 256>>>(x);

    // layer 1 (Fin=3)
    k_gather3<<<(NN + 255)/256, 256>>>();
    k_layer1<<<(NN*FF)/256, 256>>>(x, W1, r1, b1);           // -> hA

    // layers 2-4: fused gather+GEMM
    k_glayer<<<NN/64, 256>>>(0, 1, W2, r2, b2);              // hA -> hB
    k_glayer<<<NN/64, 256>>>(1, 0, W3, r3, b3);              // hB -> hA
    k_glayer<<<NN/64, 256>>>(0, 1, W4, r4, b4);              // hA -> hB

    // pooling + head
    k_pool<<<(POOL_NCHUNK*16 + 255)/256, 256>>>(batch);
    k_head<<<(NG + 255)/256, 256>>>(batch, fcw, fcb, out);
}

// round 10
// speedup vs baseline: 1.5655x; 1.4900x over previous
#include <cuda_runtime.h>
#include <cuda_fp16.h>
#include <math.h>

#define NN 80000
#define NE 1280000
#define NG 512
#define FF 64
#define KP 200   // padded k-stride (halves) for fp16 tiles

// ---------------- scratch (device globals, no allocation) ----------------
__device__ __align__(16) float g_hA[NN*FF];
__device__ __align__(16) float g_hB[NN*FF];
__device__ __align__(16) float g_x4[NN*4];
__device__ __align__(16) float g_B0[NN*4];
__device__ __align__(16) float g_B1[NN*4];
__device__ __align__(16) float g_pooled[NG*FF];
__device__ __align__(16) __half g_Wt16[3*64*KP];   // per-layer [n=64][k=192] fp16, padded
__device__ int   g_cnt[NN];
__device__ int   g_cursor[NN];
__device__ int   g_off[NN+1];
__device__ int   g_bsum[320];
__device__ int   g_boff[320];
__device__ int   g_esrc[NE];
__device__ float g_eu[NE];

// ---------------- helpers ----------------
__device__ __forceinline__ void red_add_v4(float* p, float4 v) {
    asm volatile("red.global.add.v4.f32 [%0], {%1,%2,%3,%4};"
                 :: "l"(p), "f"(v.x), "f"(v.y), "f"(v.z), "f"(v.w) : "memory");
}
__device__ __forceinline__ float elu1(float v) { return v > 0.0f ? v : expm1f(v); }

__device__ __forceinline__ void mma16816(float* c, unsigned a0, unsigned a1,
                                         unsigned a2, unsigned a3,
                                         unsigned b0, unsigned b1) {
    asm volatile(
        "mma.sync.aligned.m16n8k16.row.col.f32.f16.f16.f32 "
        "{%0,%1,%2,%3}, {%4,%5,%6,%7}, {%8,%9}, {%0,%1,%2,%3};\n"
        : "+f"(c[0]), "+f"(c[1]), "+f"(c[2]), "+f"(c[3])
        : "r"(a0), "r"(a1), "r"(a2), "r"(a3), "r"(b0), "r"(b1));
}

// ---------------- CSR build ----------------
__global__ void k_zero() {
    int t = blockIdx.x * blockDim.x + threadIdx.x;
    if (t < NN) { g_cnt[t] = 0; g_cursor[t] = 0; }
    if (t < NG*FF) g_pooled[t] = 0.0f;
}

__global__ void k_hist(const int* __restrict__ dst) {
    int e = blockIdx.x * blockDim.x + threadIdx.x;   // exactly NE threads
    atomicAdd(&g_cnt[dst[e]], 1);
}

__global__ void k_scan1() {
    __shared__ int wsum[8];
    int b = blockIdx.x, tid = threadIdx.x, lane = tid & 31, w = tid >> 5;
    int i = b * 256 + tid;
    int v = (i < NN) ? g_cnt[i] : 0;
    int inc = v;
    #pragma unroll
    for (int o = 1; o < 32; o <<= 1) {
        int nv = __shfl_up_sync(0xffffffffu, inc, o);
        if (lane >= o) inc += nv;
    }
    if (lane == 31) wsum[w] = inc;
    __syncthreads();
    if (w == 0 && lane < 8) {
        int x = wsum[lane];
        int xi = x;
        #pragma unroll
        for (int o = 1; o < 8; o <<= 1) {
            int nv = __shfl_up_sync(0xffu, xi, o, 8);
            if (lane >= o) xi += nv;
        }
        wsum[lane] = xi - x;
        if (lane == 7) g_bsum[b] = xi;
    }
    __syncthreads();
    if (i < NN) g_off[i] = wsum[w] + (inc - v);
}

#define NB_SCAN 313
__global__ void k_scan2() {
    __shared__ int s[512];
    int tid = threadIdx.x;
    int v = (tid < NB_SCAN) ? g_bsum[tid] : 0;
    s[tid] = v;
    __syncthreads();
    for (int o = 1; o < 512; o <<= 1) {
        int t = (tid >= o) ? s[tid - o] : 0;
        __syncthreads();
        s[tid] += t;
        __syncthreads();
    }
    if (tid < NB_SCAN) g_boff[tid] = s[tid] - v;
}

__global__ void k_scan3() {
    int i = blockIdx.x * blockDim.x + threadIdx.x;
    if (i < NN) g_off[i] += g_boff[i >> 8];
    if (i == 0) g_off[NN] = NE;
}

__global__ void k_fill(const int* __restrict__ src, const int* __restrict__ dst,
                       const float* __restrict__ u) {
    int e = blockIdx.x * blockDim.x + threadIdx.x;
    int d = dst[e];
    int pos = g_off[d] + atomicAdd(&g_cursor[d], 1);
    g_esrc[pos] = src[e];
    g_eu[pos]   = u[e];
}

// ---------------- pack x into float4 ----------------
__global__ void k_packx(const float* __restrict__ x) {
    int n = blockIdx.x * blockDim.x + threadIdx.x;
    if (n >= NN) return;
    float4 v; v.x = x[n*3+0]; v.y = x[n*3+1]; v.z = x[n*3+2]; v.w = 0.f;
    ((float4*)g_x4)[n] = v;
}

// ---------------- weight convert: Wt16[l][n][k] = fp16(Wcat[k][n]) ---------
__global__ void k_cvtw(const float* __restrict__ W, const float* __restrict__ root,
                       int layer) {
    int t = blockIdx.x * blockDim.x + threadIdx.x;   // 64*192 threads
    if (t >= 64*192) return;
    int n = t / 192, k = t % 192;
    float v = (k < 128) ? W[k*64 + n] : root[(k-128)*64 + n];
    g_Wt16[layer*64*KP + n*KP + k] = __float2half_rn(v);
}

// ---------------- layer 1: aggregate raw x (3-dim) then transform ----------
__global__ void k_gather3() {
    int n = blockIdx.x * blockDim.x + threadIdx.x;
    if (n >= NN) return;
    int beg = g_off[n], end = g_off[n+1];
    float sa0=0,sa1=0,sa2=0, ta0=0,ta1=0,ta2=0;
    float sb0=0,sb1=0,sb2=0, tb0=0,tb1=0,tb2=0;
    const float4* X4 = (const float4*)g_x4;
    int e = beg;
    for (; e + 1 < end; e += 2) {
        int sA = __ldg(&g_esrc[e]);   float uA = __ldg(&g_eu[e]);
        int sB = __ldg(&g_esrc[e+1]); float uB = __ldg(&g_eu[e+1]);
        float4 xa = __ldg(&X4[sA]);
        float4 xb = __ldg(&X4[sB]);
        sa0 += xa.x; sa1 += xa.y; sa2 += xa.z;
        ta0 += uA*xa.x; ta1 += uA*xa.y; ta2 += uA*xa.z;
        sb0 += xb.x; sb1 += xb.y; sb2 += xb.z;
        tb0 += uB*xb.x; tb1 += uB*xb.y; tb2 += uB*xb.z;
    }
    if (e < end) {
        int sA = __ldg(&g_esrc[e]); float uA = __ldg(&g_eu[e]);
        float4 xa = __ldg(&X4[sA]);
        sa0 += xa.x; sa1 += xa.y; sa2 += xa.z;
        ta0 += uA*xa.x; ta1 += uA*xa.y; ta2 += uA*xa.z;
    }
    float t0 = ta0+tb0, t1 = ta1+tb1, t2 = ta2+tb2;
    g_B0[n*4+0] = (sa0+sb0) - t0; g_B0[n*4+1] = (sa1+sb1) - t1; g_B0[n*4+2] = (sa2+sb2) - t2;
    g_B1[n*4+0] = t0; g_B1[n*4+1] = t1; g_B1[n*4+2] = t2;
}

__global__ void k_layer1(const float* __restrict__ x, const float* __restrict__ W,
                         const float* __restrict__ root, const float* __restrict__ b) {
    int t = blockIdx.x * blockDim.x + threadIdx.x;
    int n = t >> 6, f = t & 63;
    float agg = g_B0[n*4+0]*__ldg(&W[f])      + g_B0[n*4+1]*__ldg(&W[64+f])  + g_B0[n*4+2]*__ldg(&W[128+f])
              + g_B1[n*4+0]*__ldg(&W[192+f])  + g_B1[n*4+1]*__ldg(&W[256+f]) + g_B1[n*4+2]*__ldg(&W[320+f]);
    int dg = g_off[n+1] - g_off[n];
    float inv = 1.0f / (dg < 1 ? 1 : dg);
    float yr = x[n*3+0]*__ldg(&root[f]) + x[n*3+1]*__ldg(&root[64+f]) + x[n*3+2]*__ldg(&root[128+f]);
    g_hA[t] = elu1(agg*inv + yr + __ldg(&b[f]));
}

// ---------------- fused gather + tensor-core GEMM layer (layers 2-4) -------
// F = [A0*inv | A1*inv | H] (64 x 192, fp16 in smem, row pad KP=200)
// h_out = elu( F @ Wt^T + b ), Wt fp16 [n=64][k=192] in global.
__global__ __launch_bounds__(256) void k_glayer(int insel, int outsel, int layer,
                                                const float* __restrict__ bias) {
    __shared__ __half sA[64 * KP];                  // 25600 B
    const float* hin  = insel  ? g_hB : g_hA;
    float*       hout = outsel ? g_hB : g_hA;
    const int nb = blockIdx.x * 64;
    const int tid = threadIdx.x;
    const int lane = tid & 31;
    const int warp = tid >> 5;
    const int j = lane & 15;
    const int half = lane >> 4;

    const float4* H4 = (const float4*)hin;

    // stage H rows (fp32 -> fp16) into sA[.][128..191]
    for (int i = tid; i < 64*16; i += 256) {
        int r = i >> 4, jj = i & 15;
        float4 v = H4[(long)(nb + r)*16 + jj];
        __half2 h0 = __floats2half2_rn(v.x, v.y);
        __half2 h1 = __floats2half2_rn(v.z, v.w);
        uint2 pk; pk.x = *(unsigned*)&h0; pk.y = *(unsigned*)&h1;
        *(uint2*)&sA[r*KP + 128 + 4*jj] = pk;
    }

    // gather: 1 warp per node, 2 edges in flight per half-warp (R6 structure)
    for (int q = 0; q < 8; ++q) {
        int n = nb + warp*8 + q;
        int beg = g_off[n], end = g_off[n+1];
        int d = end - beg;
        float inv = 1.0f / (d < 1 ? 1 : d);
        int mid = beg + ((d + 1) >> 1);
        int e0 = half ? mid : beg;
        int e1 = half ? end : mid;
        float4 sa = make_float4(0.f,0.f,0.f,0.f), ta = make_float4(0.f,0.f,0.f,0.f);
        float4 sb = make_float4(0.f,0.f,0.f,0.f), tb = make_float4(0.f,0.f,0.f,0.f);
        int e = e0;
        for (; e + 1 < e1; e += 2) {
            int  iA = __ldg(&g_esrc[e]);
            int  iB = __ldg(&g_esrc[e+1]);
            float uA = __ldg(&g_eu[e]);
            float uB = __ldg(&g_eu[e+1]);
            float4 vA = H4[(long)iA*16 + j];
            float4 vB = H4[(long)iB*16 + j];
            sa.x += vA.x; sa.y += vA.y; sa.z += vA.z; sa.w += vA.w;
            ta.x += uA*vA.x; ta.y += uA*vA.y; ta.z += uA*vA.z; ta.w += uA*vA.w;
            sb.x += vB.x; sb.y += vB.y; sb.z += vB.z; sb.w += vB.w;
            tb.x += uB*vB.x; tb.y += uB*vB.y; tb.z += uB*vB.z; tb.w += uB*vB.w;
        }
        if (e < e1) {
            int  iA = __ldg(&g_esrc[e]);
            float uA = __ldg(&g_eu[e]);
            float4 vA = H4[(long)iA*16 + j];
            sa.x += vA.x; sa.y += vA.y; sa.z += vA.z; sa.w += vA.w;
            ta.x += uA*vA.x; ta.y += uA*vA.y; ta.z += uA*vA.z; ta.w += uA*vA.w;
        }
        float4 sum, t;
        sum.x = sa.x + sb.x; sum.y = sa.y + sb.y; sum.z = sa.z + sb.z; sum.w = sa.w + sb.w;
        t.x = ta.x + tb.x; t.y = ta.y + tb.y; t.z = ta.z + tb.z; t.w = ta.w + tb.w;
        sum.x += __shfl_xor_sync(0xffffffffu, sum.x, 16);
        sum.y += __shfl_xor_sync(0xffffffffu, sum.y, 16);
        sum.z += __shfl_xor_sync(0xffffffffu, sum.z, 16);
        sum.w += __shfl_xor_sync(0xffffffffu, sum.w, 16);
        t.x += __shfl_xor_sync(0xffffffffu, t.x, 16);
        t.y += __shfl_xor_sync(0xffffffffu, t.y, 16);
        t.z += __shfl_xor_sync(0xffffffffu, t.z, 16);
        t.w += __shfl_xor_sync(0xffffffffu, t.w, 16);
        int r = warp*8 + q;
        float4 o;
        if (half == 0) {   // A0 = (sum - t) * inv, k = [0,64)
            o.x = (sum.x - t.x) * inv; o.y = (sum.y - t.y) * inv;
            o.z = (sum.z - t.z) * inv; o.w = (sum.w - t.w) * inv;
        } else {           // A1 = t * inv, k = [64,128)
            o.x = t.x * inv; o.y = t.y * inv; o.z = t.z * inv; o.w = t.w * inv;
        }
        __half2 h0 = __floats2half2_rn(o.x, o.y);
        __half2 h1 = __floats2half2_rn(o.z, o.w);
        uint2 pk; pk.x = *(unsigned*)&h0; pk.y = *(unsigned*)&h1;
        *(uint2*)&sA[r*KP + half*64 + 4*j] = pk;
    }
    __syncthreads();

    // tensor-core GEMM: warp -> m16 x n32 tile; 12 k-chunks of 16
    const int g  = lane >> 2;       // group id 0..7
    const int tg = lane & 3;        // thread-in-group 0..3
    const int mtile = warp & 3;     // rows 16*mtile
    const int nhalf = warp >> 2;    // cols 32*nhalf
    const int mb = mtile * 16;

    const __half* Wt = g_Wt16 + layer*64*KP;

    float acc[4][4];
    #pragma unroll
    for (int nt = 0; nt < 4; ++nt)
        #pragma unroll
        for (int c = 0; c < 4; ++c) acc[nt][c] = 0.f;

    #pragma unroll
    for (int kc = 0; kc < 12; ++kc) {
        int kb = kc * 16;
        const __half* pa = &sA[(mb + g)*KP + kb + 2*tg];
        unsigned a0 = *(const unsigned*)(pa);
        unsigned a1 = *(const unsigned*)(pa + 8*KP);
        unsigned a2 = *(const unsigned*)(pa + 8);
        unsigned a3 = *(const unsigned*)(pa + 8*KP + 8);
        #pragma unroll
        for (int nt = 0; nt < 4; ++nt) {
            int ncol = nhalf*32 + nt*8 + g;
            const __half* pb = &Wt[ncol*KP + kb + 2*tg];
            unsigned b0 = __ldg((const unsigned*)(pb));
            unsigned b1 = __ldg((const unsigned*)(pb + 8));
            mma16816(acc[nt], a0, a1, a2, a3, b0, b1);
        }
    }

    // epilogue: bias + elu, write fp32 h
    #pragma unroll
    for (int nt = 0; nt < 4; ++nt) {
        int col = nhalf*32 + nt*8 + 2*tg;
        float2 bv = *(const float2*)&bias[col];
        int m0 = nb + mb + g;
        float2 o0, o1;
        o0.x = elu1(acc[nt][0] + bv.x);
        o0.y = elu1(acc[nt][1] + bv.y);
        o1.x = elu1(acc[nt][2] + bv.x);
        o1.y = elu1(acc[nt][3] + bv.y);
        *(float2*)&hout[(long)m0*64 + col]       = o0;
        *(float2*)&hout[(long)(m0+8)*64 + col]   = o1;
    }
}

// ---------------- pooling ----------------
#define POOL_CHUNK 64
#define POOL_NCHUNK ((NN + POOL_CHUNK - 1) / POOL_CHUNK)   // 1250
__global__ void k_pool(const int* __restrict__ batch) {
    int t = blockIdx.x * blockDim.x + threadIdx.x;
    int j = t & 15;
    int c = t >> 4;
    if (c >= POOL_NCHUNK) return;
    int n0 = c * POOL_CHUNK;
    int n1 = n0 + POOL_CHUNK; if (n1 > NN) n1 = NN;
    const float4* h4 = (const float4*)g_hB;
    float4 acc = make_float4(0.f,0.f,0.f,0.f);
    int g = batch[n0];
    for (int n = n0; n < n1; ++n) {
        int gg = batch[n];
        if (gg != g) {
            red_add_v4(&g_pooled[g*64 + j*4], acc);
            acc = make_float4(0.f,0.f,0.f,0.f);
            g = gg;
        }
        float4 v = h4[(long)n*16 + j];
        acc.x += v.x; acc.y += v.y; acc.z += v.z; acc.w += v.w;
    }
    red_add_v4(&g_pooled[g*64 + j*4], acc);
}

// ---------------- head ----------------
__global__ void k_head(const int* __restrict__ batch, const float* __restrict__ fcw,
                       const float* __restrict__ fcb, float* __restrict__ out) {
    int g = blockIdx.x * blockDim.x + threadIdx.x;
    if (g >= NG) return;
    int lo, hi, c0, c1;
    lo = 0; hi = NN;
    while (lo < hi) { int mid = (lo + hi) >> 1; if (batch[mid] < g) lo = mid + 1; else hi = mid; }
    c0 = lo;
    lo = 0; hi = NN;
    while (lo < hi) { int mid = (lo + hi) >> 1; if (batch[mid] < g + 1) lo = mid + 1; else hi = mid; }
    c1 = lo;
    float cnt = (float)(c1 - c0);
    float inv = 1.0f / (cnt < 1.0f ? 1.0f : cnt);

    float logit[6];
    #pragma unroll
    for (int cc = 0; cc < 6; ++cc) logit[cc] = fcb[cc];
    for (int k = 0; k < 64; ++k) {
        float p = g_pooled[g*64 + k] * inv;
        #pragma unroll
        for (int cc = 0; cc < 6; ++cc) logit[cc] += p * fcw[k*6 + cc];
    }
    float m = logit[0];
    #pragma unroll
    for (int cc = 1; cc < 6; ++cc) m = fmaxf(m, logit[cc]);
    float s = 0.f;
    #pragma unroll
    for (int cc = 0; cc < 6; ++cc) s += expf(logit[cc] - m);
    float l = logf(s);
    #pragma unroll
    for (int cc = 0; cc < 6; ++cc) out[g*6 + cc] = logit[cc] - m - l;
}

// ---------------- launch ----------------
extern "C" void kernel_launch(void* const* d_in, const int* in_sizes, int n_in,
                              void* d_out, int out_size) {
    const float* x      = (const float*)d_in[0];
    const float* pseudo = (const float*)d_in[1];
    const int*   ei     = (const int*)d_in[2];
    const int*   batch  = (const int*)d_in[3];
    const float* W1 = (const float*)d_in[4];
    const float* r1 = (const float*)d_in[5];
    const float* b1 = (const float*)d_in[6];
    const float* W2 = (const float*)d_in[7];
    const float* r2 = (const float*)d_in[8];
    const float* b2 = (const float*)d_in[9];
    const float* W3 = (const float*)d_in[10];
    const float* r3 = (const float*)d_in[11];
    const float* b3 = (const float*)d_in[12];
    const float* W4 = (const float*)d_in[13];
    const float* r4 = (const float*)d_in[14];
    const float* b4 = (const float*)d_in[15];
    const float* fcw = (const float*)d_in[16];
    const float* fcb = (const float*)d_in[17];
    float* out = (float*)d_out;

    const int* src = ei;
    const int* dst = ei + NE;

    // CSR build
    k_zero<<<(NN + 255)/256, 256>>>();
    k_hist<<<NE/256, 256>>>(dst);
    k_scan1<<<NB_SCAN, 256>>>();
    k_scan2<<<1, 512>>>();
    k_scan3<<<NB_SCAN, 256>>>();
    k_fill<<<NE/256, 256>>>(src, dst, pseudo);
    k_packx<<<(NN + 255)/256, 256>>>(x);

    // fp16 transposed weights for layers 2-4
    k_cvtw<<<(64*192 + 255)/256, 256>>>(W2, r2, 0);
    k_cvtw<<<(64*192 + 255)/256, 256>>>(W3, r3, 1);
    k_cvtw<<<(64*192 + 255)/256, 256>>>(W4, r4, 2);

    // layer 1 (Fin=3)
    k_gather3<<<(NN + 255)/256, 256>>>();
    k_layer1<<<(NN*FF)/256, 256>>>(x, W1, r1, b1);           // -> hA

    // layers 2-4: fused gather + tensor-core GEMM
    k_glayer<<<NN/64, 256>>>(0, 1, 0, b2);                   // hA -> hB
    k_glayer<<<NN/64, 256>>>(1, 0, 1, b3);                   // hB -> hA
    k_glayer<<<NN/64, 256>>>(0, 1, 2, b4);                   // hA -> hB

    // pooling + head
    k_pool<<<(POOL_NCHUNK*16 + 255)/256, 256>>>(batch);
    k_head<<<(NG + 255)/256, 256>>>(batch, fcw, fcb, out);
}

// round 11
// speedup vs baseline: 1.6764x; 1.0708x over previous
#include <cuda_runtime.h>
#include <cuda_fp16.h>
#include <math.h>

#define NN 80000
#define NE 1280000
#define NG 512
#define FF 64
#define KP 200   // padded k-stride (halves) for fp16 tiles

// ---------------- scratch (device globals, no allocation) ----------------
__device__ __align__(16) float g_hA[NN*FF];
__device__ __align__(16) float g_hB[NN*FF];
__device__ __align__(16) float g_x4[NN*4];
__device__ __align__(16) float g_B0[NN*4];
__device__ __align__(16) float g_B1[NN*4];
__device__ __align__(16) float g_pooled[NG*FF];
__device__ __align__(16) __half g_Wt16[3*64*KP];   // per-layer [n=64][k=192] fp16, padded
__device__ int   g_cnt[NN];
__device__ int   g_cursor[NN];
__device__ int   g_off[NN+1];
__device__ int   g_bsum[320];
__device__ int   g_boff[320];
__device__ __align__(16) int2 g_edge[NE];          // {src, u bits}

// ---------------- helpers ----------------
__device__ __forceinline__ void red_add_v4(float* p, float4 v) {
    asm volatile("red.global.add.v4.f32 [%0], {%1,%2,%3,%4};"
                 :: "l"(p), "f"(v.x), "f"(v.y), "f"(v.z), "f"(v.w) : "memory");
}
__device__ __forceinline__ float elu1(float v) { return v > 0.0f ? v : expm1f(v); }

__device__ __forceinline__ void mma16816(float* c, unsigned a0, unsigned a1,
                                         unsigned a2, unsigned a3,
                                         unsigned b0, unsigned b1) {
    asm volatile(
        "mma.sync.aligned.m16n8k16.row.col.f32.f16.f16.f32 "
        "{%0,%1,%2,%3}, {%4,%5,%6,%7}, {%8,%9}, {%0,%1,%2,%3};\n"
        : "+f"(c[0]), "+f"(c[1]), "+f"(c[2]), "+f"(c[3])
        : "r"(a0), "r"(a1), "r"(a2), "r"(a3), "r"(b0), "r"(b1));
}

// ---------------- prep: zero counters/pooled + pack x --------------------
__global__ void k_prep(const float* __restrict__ x) {
    int t = blockIdx.x * blockDim.x + threadIdx.x;
    if (t < NN) {
        g_cnt[t] = 0; g_cursor[t] = 0;
        float4 v; v.x = x[t*3+0]; v.y = x[t*3+1]; v.z = x[t*3+2]; v.w = 0.f;
        ((float4*)g_x4)[t] = v;
    }
    if (t < NG*FF) g_pooled[t] = 0.0f;
}

__global__ void k_hist(const int* __restrict__ dst) {
    int e = blockIdx.x * blockDim.x + threadIdx.x;   // exactly NE threads
    atomicAdd(&g_cnt[dst[e]], 1);
}

__global__ void k_scan1() {
    __shared__ int wsum[8];
    int b = blockIdx.x, tid = threadIdx.x, lane = tid & 31, w = tid >> 5;
    int i = b * 256 + tid;
    int v = (i < NN) ? g_cnt[i] : 0;
    int inc = v;
    #pragma unroll
    for (int o = 1; o < 32; o <<= 1) {
        int nv = __shfl_up_sync(0xffffffffu, inc, o);
        if (lane >= o) inc += nv;
    }
    if (lane == 31) wsum[w] = inc;
    __syncthreads();
    if (w == 0 && lane < 8) {
        int x = wsum[lane];
        int xi = x;
        #pragma unroll
        for (int o = 1; o < 8; o <<= 1) {
            int nv = __shfl_up_sync(0xffu, xi, o, 8);
            if (lane >= o) xi += nv;
        }
        wsum[lane] = xi - x;
        if (lane == 7) g_bsum[b] = xi;
    }
    __syncthreads();
    if (i < NN) g_off[i] = wsum[w] + (inc - v);
}

#define NB_SCAN 313
__global__ void k_scan2() {
    __shared__ int s[512];
    int tid = threadIdx.x;
    int v = (tid < NB_SCAN) ? g_bsum[tid] : 0;
    s[tid] = v;
    __syncthreads();
    for (int o = 1; o < 512; o <<= 1) {
        int t = (tid >= o) ? s[tid - o] : 0;
        __syncthreads();
        s[tid] += t;
        __syncthreads();
    }
    if (tid < NB_SCAN) g_boff[tid] = s[tid] - v;
}

__global__ void k_scan3() {
    int i = blockIdx.x * blockDim.x + threadIdx.x;
    if (i < NN) g_off[i] += g_boff[i >> 8];
    if (i == 0) g_off[NN] = NE;
}

__global__ void k_fill(const int* __restrict__ src, const int* __restrict__ dst,
                       const float* __restrict__ u) {
    int e = blockIdx.x * blockDim.x + threadIdx.x;
    int d = dst[e];
    int pos = g_off[d] + atomicAdd(&g_cursor[d], 1);
    g_edge[pos] = make_int2(src[e], __float_as_int(u[e]));
}

// ---------------- weight convert: Wt16[l][n][k] = fp16(Wcat[k][n]) ---------
__global__ void k_cvtw(const float* __restrict__ Wa, const float* __restrict__ ra,
                       const float* __restrict__ Wb, const float* __restrict__ rb,
                       const float* __restrict__ Wc, const float* __restrict__ rc) {
    int t = blockIdx.x * blockDim.x + threadIdx.x;   // 3*64*192 threads
    if (t >= 3*64*192) return;
    int layer = t / (64*192);
    int r = t % (64*192);
    int n = r / 192, k = r % 192;
    const float* W    = (layer == 0) ? Wa : (layer == 1) ? Wb : Wc;
    const float* root = (layer == 0) ? ra : (layer == 1) ? rb : rc;
    float v = (k < 128) ? W[k*64 + n] : root[(k-128)*64 + n];
    g_Wt16[layer*64*KP + n*KP + k] = __float2half_rn(v);
}

// ---------------- layer 1: aggregate raw x (3-dim) then transform ----------
__global__ void k_gather3() {
    int n = blockIdx.x * blockDim.x + threadIdx.x;
    if (n >= NN) return;
    int beg = g_off[n], end = g_off[n+1];
    float sa0=0,sa1=0,sa2=0, ta0=0,ta1=0,ta2=0;
    float sb0=0,sb1=0,sb2=0, tb0=0,tb1=0,tb2=0;
    const float4* X4 = (const float4*)g_x4;
    int e = beg;
    for (; e + 1 < end; e += 2) {
        int2 eA = __ldg(&g_edge[e]);
        int2 eB = __ldg(&g_edge[e+1]);
        float uA = __int_as_float(eA.y);
        float uB = __int_as_float(eB.y);
        float4 xa = __ldg(&X4[eA.x]);
        float4 xb = __ldg(&X4[eB.x]);
        sa0 += xa.x; sa1 += xa.y; sa2 += xa.z;
        ta0 += uA*xa.x; ta1 += uA*xa.y; ta2 += uA*xa.z;
        sb0 += xb.x; sb1 += xb.y; sb2 += xb.z;
        tb0 += uB*xb.x; tb1 += uB*xb.y; tb2 += uB*xb.z;
    }
    if (e < end) {
        int2 eA = __ldg(&g_edge[e]);
        float uA = __int_as_float(eA.y);
        float4 xa = __ldg(&X4[eA.x]);
        sa0 += xa.x; sa1 += xa.y; sa2 += xa.z;
        ta0 += uA*xa.x; ta1 += uA*xa.y; ta2 += uA*xa.z;
    }
    float t0 = ta0+tb0, t1 = ta1+tb1, t2 = ta2+tb2;
    g_B0[n*4+0] = (sa0+sb0) - t0; g_B0[n*4+1] = (sa1+sb1) - t1; g_B0[n*4+2] = (sa2+sb2) - t2;
    g_B1[n*4+0] = t0; g_B1[n*4+1] = t1; g_B1[n*4+2] = t2;
}

__global__ void k_layer1(const float* __restrict__ x, const float* __restrict__ W,
                         const float* __restrict__ root, const float* __restrict__ b) {
    int t = blockIdx.x * blockDim.x + threadIdx.x;
    int n = t >> 6, f = t & 63;
    float agg = g_B0[n*4+0]*__ldg(&W[f])      + g_B0[n*4+1]*__ldg(&W[64+f])  + g_B0[n*4+2]*__ldg(&W[128+f])
              + g_B1[n*4+0]*__ldg(&W[192+f])  + g_B1[n*4+1]*__ldg(&W[256+f]) + g_B1[n*4+2]*__ldg(&W[320+f]);
    int dg = g_off[n+1] - g_off[n];
    float inv = 1.0f / (dg < 1 ? 1 : dg);
    float yr = x[n*3+0]*__ldg(&root[f]) + x[n*3+1]*__ldg(&root[64+f]) + x[n*3+2]*__ldg(&root[128+f]);
    g_hA[t] = elu1(agg*inv + yr + __ldg(&b[f]));
}

// ---------------- fused gather + tensor-core GEMM layer (layers 2-4) -------
// F = [A0*inv | A1*inv | H] (64 x 192, fp16 in smem, row pad KP=200)
// h_out = elu( F @ Wt^T + b ), Wt fp16 [n=64][k=192] in global.
__global__ __launch_bounds__(256) void k_glayer(int insel, int outsel, int layer,
                                                const float* __restrict__ bias) {
    __shared__ __half sA[64 * KP];                  // 25600 B
    const float* hin  = insel  ? g_hB : g_hA;
    float*       hout = outsel ? g_hB : g_hA;
    const int nb = blockIdx.x * 64;
    const int tid = threadIdx.x;
    const int lane = tid & 31;
    const int warp = tid >> 5;
    const int j = lane & 15;
    const int half = lane >> 4;

    const float4* H4 = (const float4*)hin;

    // stage H rows (fp32 -> fp16) into sA[.][128..191]
    for (int i = tid; i < 64*16; i += 256) {
        int r = i >> 4, jj = i & 15;
        float4 v = H4[(long)(nb + r)*16 + jj];
        __half2 h0 = __floats2half2_rn(v.x, v.y);
        __half2 h1 = __floats2half2_rn(v.z, v.w);
        uint2 pk; pk.x = *(unsigned*)&h0; pk.y = *(unsigned*)&h1;
        *(uint2*)&sA[r*KP + 128 + 4*jj] = pk;
    }

    // gather: 1 warp per node, 2 edges in flight per half-warp
    for (int q = 0; q < 8; ++q) {
        int n = nb + warp*8 + q;
        int beg = g_off[n], end = g_off[n+1];
        int d = end - beg;
        float inv = 1.0f / (d < 1 ? 1 : d);
        int mid = beg + ((d + 1) >> 1);
        int e0 = half ? mid : beg;
        int e1 = half ? end : mid;
        float4 sa = make_float4(0.f,0.f,0.f,0.f), ta = make_float4(0.f,0.f,0.f,0.f);
        float4 sb = make_float4(0.f,0.f,0.f,0.f), tb = make_float4(0.f,0.f,0.f,0.f);
        int e = e0;
        for (; e + 1 < e1; e += 2) {
            int2 eA = __ldg(&g_edge[e]);
            int2 eB = __ldg(&g_edge[e+1]);
            float uA = __int_as_float(eA.y);
            float uB = __int_as_float(eB.y);
            float4 vA = H4[(long)eA.x*16 + j];
            float4 vB = H4[(long)eB.x*16 + j];
            sa.x += vA.x; sa.y += vA.y; sa.z += vA.z; sa.w += vA.w;
            ta.x += uA*vA.x; ta.y += uA*vA.y; ta.z += uA*vA.z; ta.w += uA*vA.w;
            sb.x += vB.x; sb.y += vB.y; sb.z += vB.z; sb.w += vB.w;
            tb.x += uB*vB.x; tb.y += uB*vB.y; tb.z += uB*vB.z; tb.w += uB*vB.w;
        }
        if (e < e1) {
            int2 eA = __ldg(&g_edge[e]);
            float uA = __int_as_float(eA.y);
            float4 vA = H4[(long)eA.x*16 + j];
            sa.x += vA.x; sa.y += vA.y; sa.z += vA.z; sa.w += vA.w;
            ta.x += uA*vA.x; ta.y += uA*vA.y; ta.z += uA*vA.z; ta.w += uA*vA.w;
        }
        float4 sum, t;
        sum.x = sa.x + sb.x; sum.y = sa.y + sb.y; sum.z = sa.z + sb.z; sum.w = sa.w + sb.w;
        t.x = ta.x + tb.x; t.y = ta.y + tb.y; t.z = ta.z + tb.z; t.w = ta.w + tb.w;
        sum.x += __shfl_xor_sync(0xffffffffu, sum.x, 16);
        sum.y += __shfl_xor_sync(0xffffffffu, sum.y, 16);
        sum.z += __shfl_xor_sync(0xffffffffu, sum.z, 16);
        sum.w += __shfl_xor_sync(0xffffffffu, sum.w, 16);
        t.x += __shfl_xor_sync(0xffffffffu, t.x, 16);
        t.y += __shfl_xor_sync(0xffffffffu, t.y, 16);
        t.z += __shfl_xor_sync(0xffffffffu, t.z, 16);
        t.w += __shfl_xor_sync(0xffffffffu, t.w, 16);
        int r = warp*8 + q;
        float4 o;
        if (half == 0) {   // A0 = (sum - t) * inv, k = [0,64)
            o.x = (sum.x - t.x) * inv; o.y = (sum.y - t.y) * inv;
            o.z = (sum.z - t.z) * inv; o.w = (sum.w - t.w) * inv;
        } else {           // A1 = t * inv, k = [64,128)
            o.x = t.x * inv; o.y = t.y * inv; o.z = t.z * inv; o.w = t.w * inv;
        }
        __half2 h0 = __floats2half2_rn(o.x, o.y);
        __half2 h1 = __floats2half2_rn(o.z, o.w);
        uint2 pk; pk.x = *(unsigned*)&h0; pk.y = *(unsigned*)&h1;
        *(uint2*)&sA[r*KP + half*64 + 4*j] = pk;
    }
    __syncthreads();

    // tensor-core GEMM: warp -> m16 x n32 tile; 12 k-chunks of 16
    const int g  = lane >> 2;       // group id 0..7
    const int tg = lane & 3;        // thread-in-group 0..3
    const int mtile = warp & 3;     // rows 16*mtile
    const int nhalf = warp >> 2;    // cols 32*nhalf
    const int mb = mtile * 16;

    const __half* Wt = g_Wt16 + layer*64*KP;

    float acc[4][4];
    #pragma unroll
    for (int nt = 0; nt < 4; ++nt)
        #pragma unroll
        for (int c = 0; c < 4; ++c) acc[nt][c] = 0.f;

    #pragma unroll
    for (int kc = 0; kc < 12; ++kc) {
        int kb = kc * 16;
        const __half* pa = &sA[(mb + g)*KP + kb + 2*tg];
        unsigned a0 = *(const unsigned*)(pa);
        unsigned a1 = *(const unsigned*)(pa + 8*KP);
        unsigned a2 = *(const unsigned*)(pa + 8);
        unsigned a3 = *(const unsigned*)(pa + 8*KP + 8);
        #pragma unroll
        for (int nt = 0; nt < 4; ++nt) {
            int ncol = nhalf*32 + nt*8 + g;
            const __half* pb = &Wt[ncol*KP + kb + 2*tg];
            unsigned b0 = __ldg((const unsigned*)(pb));
            unsigned b1 = __ldg((const unsigned*)(pb + 8));
            mma16816(acc[nt], a0, a1, a2, a3, b0, b1);
        }
    }

    // epilogue: bias + elu, write fp32 h
    #pragma unroll
    for (int nt = 0; nt < 4; ++nt) {
        int col = nhalf*32 + nt*8 + 2*tg;
        float2 bv = *(const float2*)&bias[col];
        int m0 = nb + mb + g;
        float2 o0, o1;
        o0.x = elu1(acc[nt][0] + bv.x);
        o0.y = elu1(acc[nt][1] + bv.y);
        o1.x = elu1(acc[nt][2] + bv.x);
        o1.y = elu1(acc[nt][3] + bv.y);
        *(float2*)&hout[(long)m0*64 + col]       = o0;
        *(float2*)&hout[(long)(m0+8)*64 + col]   = o1;
    }
}

// ---------------- pooling ----------------
#define POOL_CHUNK 64
#define POOL_NCHUNK ((NN + POOL_CHUNK - 1) / POOL_CHUNK)   // 1250
__global__ void k_pool(const int* __restrict__ batch) {
    int t = blockIdx.x * blockDim.x + threadIdx.x;
    int j = t & 15;
    int c = t >> 4;
    if (c >= POOL_NCHUNK) return;
    int n0 = c * POOL_CHUNK;
    int n1 = n0 + POOL_CHUNK; if (n1 > NN) n1 = NN;
    const float4* h4 = (const float4*)g_hB;
    float4 acc = make_float4(0.f,0.f,0.f,0.f);
    int g = batch[n0];
    for (int n = n0; n < n1; ++n) {
        int gg = batch[n];
        if (gg != g) {
            red_add_v4(&g_pooled[g*64 + j*4], acc);
            acc = make_float4(0.f,0.f,0.f,0.f);
            g = gg;
        }
        float4 v = h4[(long)n*16 + j];
        acc.x += v.x; acc.y += v.y; acc.z += v.z; acc.w += v.w;
    }
    red_add_v4(&g_pooled[g*64 + j*4], acc);
}

// ---------------- head ----------------
__global__ void k_head(const int* __restrict__ batch, const float* __restrict__ fcw,
                       const float* __restrict__ fcb, float* __restrict__ out) {
    int g = blockIdx.x * blockDim.x + threadIdx.x;
    if (g >= NG) return;
    int lo, hi, c0, c1;
    lo = 0; hi = NN;
    while (lo < hi) { int mid = (lo + hi) >> 1; if (batch[mid] < g) lo = mid + 1; else hi = mid; }
    c0 = lo;
    lo = 0; hi = NN;
    while (lo < hi) { int mid = (lo + hi) >> 1; if (batch[mid] < g + 1) lo = mid + 1; else hi = mid; }
    c1 = lo;
    float cnt = (float)(c1 - c0);
    float inv = 1.0f / (cnt < 1.0f ? 1.0f : cnt);

    float logit[6];
    #pragma unroll
    for (int cc = 0; cc < 6; ++cc) logit[cc] = fcb[cc];
    for (int k = 0; k < 64; ++k) {
        float p = g_pooled[g*64 + k] * inv;
        #pragma unroll
        for (int cc = 0; cc < 6; ++cc) logit[cc] += p * fcw[k*6 + cc];
    }
    float m = logit[0];
    #pragma unroll
    for (int cc = 1; cc < 6; ++cc) m = fmaxf(m, logit[cc]);
    float s = 0.f;
    #pragma unroll
    for (int cc = 0; cc < 6; ++cc) s += expf(logit[cc] - m);
    float l = logf(s);
    #pragma unroll
    for (int cc = 0; cc < 6; ++cc) out[g*6 + cc] = logit[cc] - m - l;
}

// ---------------- launch ----------------
extern "C" void kernel_launch(void* const* d_in, const int* in_sizes, int n_in,
                              void* d_out, int out_size) {
    const float* x      = (const float*)d_in[0];
    const float* pseudo = (const float*)d_in[1];
    const int*   ei     = (const int*)d_in[2];
    const int*   batch  = (const int*)d_in[3];
    const float* W1 = (const float*)d_in[4];
    const float* r1 = (const float*)d_in[5];
    const float* b1 = (const float*)d_in[6];
    const float* W2 = (const float*)d_in[7];
    const float* r2 = (const float*)d_in[8];
    const float* b2 = (const float*)d_in[9];
    const float* W3 = (const float*)d_in[10];
    const float* r3 = (const float*)d_in[11];
    const float* b3 = (const float*)d_in[12];
    const float* W4 = (const float*)d_in[13];
    const float* r4 = (const float*)d_in[14];
    const float* b4 = (const float*)d_in[15];
    const float* fcw = (const float*)d_in[16];
    const float* fcb = (const float*)d_in[17];
    float* out = (float*)d_out;

    const int* src = ei;
    const int* dst = ei + NE;

    // CSR build + prep
    k_prep<<<(NN + 255)/256, 256>>>(x);
    k_hist<<<NE/256, 256>>>(dst);
    k_scan1<<<NB_SCAN, 256>>>();
    k_scan2<<<1, 512>>>();
    k_scan3<<<NB_SCAN, 256>>>();
    k_fill<<<NE/256, 256>>>(src, dst, pseudo);
    k_cvtw<<<(3*64*192 + 255)/256, 256>>>(W2, r2, W3, r3, W4, r4);

    // layer 1 (Fin=3)
    k_gather3<<<(NN + 255)/256, 256>>>();
    k_layer1<<<(NN*FF)/256, 256>>>(x, W1, r1, b1);           // -> hA

    // layers 2-4: fused gather + tensor-core GEMM
    k_glayer<<<NN/64, 256>>>(0, 1, 0, b2);                   // hA -> hB
    k_glayer<<<NN/64, 256>>>(1, 0, 1, b3);                   // hB -> hA
    k_glayer<<<NN/64, 256>>>(0, 1, 2, b4);                   // hA -> hB

    // pooling + head
    k_pool<<<(POOL_NCHUNK*16 + 255)/256, 256>>>(batch);
    k_head<<<(NG + 255)/256, 256>>>(batch, fcw, fcb, out);
}